// round 13
// baseline (speedup 1.0000x reference)
#include <cuda_runtime.h>
#include <cuda_bf16.h>
#include <cuda_fp16.h>
#include <cstdint>

// ----------------------------------------------------------------------------
// PositionAttention: B=4, L=1024, HD=512, H=8, D=64
// Round 13: issue-slot diet via codegen —
//   * kb/kt loops unrolled x2 (compile-time stage parity -> [base+imm] smem
//     addressing, kills per-tile IMAD address recompute)
//   * exp-guard SEL removed (masked -1e30 underflows to exactly 0 in __expf)
// Math identical to R12 (rel_err 2.973e-4).
// ----------------------------------------------------------------------------

#define BATCH 4
#define SEQ   1024
#define HDIM  512
#define NHEAD 8
#define DHEAD 64
#define ROWS  (BATCH*SEQ)          // 4096

#define RSTR 40
#define NKT  (HDIM/32)
#define AIR  (3*ROWS)
#define WR   2048

#define KB    32
#define PADKH 72
#define PADVTH 40

__device__ __align__(16) float  g_q[ROWS * HDIM];
__device__ __align__(16) __half g_kh[(size_t)BATCH*NHEAD*SEQ*PADKH];
__device__ __align__(16) __half g_vth[(size_t)BATCH*NHEAD*(SEQ/KB)*DHEAD*PADVTH];
__device__ __align__(16) __nv_bfloat16 g_inh[(size_t)NKT*AIR*RSTR];
__device__ __align__(16) __nv_bfloat16 g_inl[(size_t)NKT*AIR*RSTR];
__device__ __align__(16) __nv_bfloat16 g_wh[(size_t)NKT*WR*RSTR];
__device__ __align__(16) __nv_bfloat16 g_wl[(size_t)NKT*WR*RSTR];
__device__ __align__(16) __nv_bfloat16 g_ah[(size_t)NKT*ROWS*RSTR];
__device__ __align__(16) __nv_bfloat16 g_al[(size_t)NKT*ROWS*RSTR];

// ============================================================================
// mbarrier / bulk-copy primitives
// ============================================================================
__device__ __forceinline__ void mbar_init(uint32_t a, uint32_t cnt) {
    asm volatile("mbarrier.init.shared.b64 [%0], %1;" :: "r"(a), "r"(cnt) : "memory");
}
__device__ __forceinline__ void mbar_expect(uint32_t a, uint32_t bytes) {
    asm volatile("mbarrier.arrive.expect_tx.shared.b64 _, [%0], %1;"
                 :: "r"(a), "r"(bytes) : "memory");
}
__device__ __forceinline__ void mbar_wait(uint32_t a, uint32_t parity) {
    asm volatile(
        "{\n\t.reg .pred P;\n\t"
        "WAIT_%=:\n\t"
        "mbarrier.try_wait.parity.acquire.cta.shared::cta.b64 P, [%0], %1, 0x989680;\n\t"
        "@P bra.uni DONE_%=;\n\t"
        "bra.uni WAIT_%=;\n\t"
        "DONE_%=:\n\t}"
        :: "r"(a), "r"(parity) : "memory");
}
__device__ __forceinline__ void bulk_g2s(uint32_t dst, const void* src,
                                         uint32_t bytes, uint32_t mbar) {
    asm volatile(
        "cp.async.bulk.shared::cta.global.mbarrier::complete_tx::bytes "
        "[%0], [%1], %2, [%3];"
        :: "r"(dst), "l"(src), "r"(bytes), "r"(mbar) : "memory");
}
__device__ __forceinline__ void fence_async_init() {
    asm volatile("fence.proxy.async.shared::cta;" ::: "memory");
}
__device__ __forceinline__ void ldsm4(uint32_t& r0, uint32_t& r1,
                                      uint32_t& r2, uint32_t& r3, uint32_t addr) {
    asm volatile("ldmatrix.sync.aligned.m8n8.x4.shared.b16 {%0,%1,%2,%3}, [%4];"
                 : "=r"(r0), "=r"(r1), "=r"(r2), "=r"(r3) : "r"(addr));
}

// ============================================================================
// split kernels (unchanged)
// ============================================================================
__device__ __forceinline__ void split8(const float* src, uint4& hw, uint4& lw)
{
    float4 a = *(const float4*)src;
    float4 b = *(const float4*)(src + 4);
    float v[8] = {a.x, a.y, a.z, a.w, b.x, b.y, b.z, b.w};
    uint32_t h[4], l[4];
#pragma unroll
    for (int i = 0; i < 4; i++) {
        __nv_bfloat16 h0 = __float2bfloat16_rn(v[2*i]);
        __nv_bfloat16 h1 = __float2bfloat16_rn(v[2*i+1]);
        __nv_bfloat16 l0 = __float2bfloat16_rn(v[2*i]   - __bfloat162float(h0));
        __nv_bfloat16 l1 = __float2bfloat16_rn(v[2*i+1] - __bfloat162float(h1));
        __nv_bfloat162 hp(h0, h1), lp(l0, l1);
        h[i] = *(uint32_t*)&hp; l[i] = *(uint32_t*)&lp;
    }
    hw = make_uint4(h[0], h[1], h[2], h[3]);
    lw = make_uint4(l[0], l[1], l[2], l[3]);
}

__global__ void __launch_bounds__(256)
split_in_kernel(const float* __restrict__ q, const float* __restrict__ k,
                const float* __restrict__ v)
{
    size_t i = (size_t)blockIdx.x * 256 + threadIdx.x;
    int mat = (int)(i / (ROWS * 64));
    size_t rem = i - (size_t)mat * (ROWS * 64);
    int r = (int)(rem >> 6);
    int kk = ((int)rem & 63) * 8;
    int kt = kk >> 5, km = kk & 31;
    const float* src = (mat == 0 ? q : mat == 1 ? k : v) + ((size_t)r << 9) + kk;
    uint4 hw, lw; split8(src, hw, lw);
    size_t d = ((size_t)kt * AIR + (size_t)mat * ROWS + r) * RSTR + km;
    *(uint4*)(g_inh + d) = hw;
    *(uint4*)(g_inl + d) = lw;
}

__global__ void __launch_bounds__(256)
split_w_kernel(const float* __restrict__ ipw, const float* __restrict__ outw)
{
    size_t i = (size_t)blockIdx.x * 256 + threadIdx.x;
    int r = (int)(i >> 6);
    int kk = ((int)i & 63) * 8;
    int kt = kk >> 5, km = kk & 31;
    const float* src = (r < 1536) ? (ipw + ((size_t)r << 9) + kk)
                                  : (outw + ((size_t)(r - 1536) << 9) + kk);
    uint4 hw, lw; split8(src, hw, lw);
    size_t d = ((size_t)kt * WR + r) * RSTR + km;
    *(uint4*)(g_wh + d) = hw;
    *(uint4*)(g_wl + d) = lw;
}

// ============================================================================
// bf16x3 GEMM, bulk 2-stage, kt loop unrolled x2.
// ============================================================================
#define TBM 128
#define TBN 128
#define MATW (TBM * RSTR / 2)
#define GSTW (4 * MATW)
#define GEMM_SMEM (2 * GSTW * 4 + 16)

__device__ __forceinline__ void mma_bf16(float c[4],
    uint32_t a0, uint32_t a1, uint32_t a2, uint32_t a3,
    uint32_t b0, uint32_t b1)
{
    asm volatile(
        "mma.sync.aligned.m16n8k16.row.col.f32.bf16.bf16.f32 "
        "{%0,%1,%2,%3}, {%4,%5,%6,%7}, {%8,%9}, {%0,%1,%2,%3};"
        : "+f"(c[0]), "+f"(c[1]), "+f"(c[2]), "+f"(c[3])
        : "r"(a0), "r"(a1), "r"(a2), "r"(a3), "r"(b0), "r"(b1));
}

__device__ __forceinline__ void gemm_core(
    const __nv_bfloat16* __restrict__ Ah, const __nv_bfloat16* __restrict__ Al,
    int AR, int arow0,
    const __nv_bfloat16* __restrict__ Bh, const __nv_bfloat16* __restrict__ Bl,
    int BR, int brow0,
    const float* __restrict__ bias, void* __restrict__ Cout, int mode,
    uint32_t* smem)
{
    const int tid  = threadIdx.x;
    const int w    = tid >> 5;
    const int lane = tid & 31;
    const int g = lane >> 2, t = lane & 3;
    const int wm = w >> 2, wn = w & 3;
    const int m0 = wm * 64, n0 = wn * 32;
    const int bm = blockIdx.y * TBM;
    const int bn = blockIdx.x * TBN;
    const uint32_t sbase = (uint32_t)__cvta_generic_to_shared(smem);
    const uint32_t mb0 = sbase + 2u * GSTW * 4u;
    const uint32_t mb1 = mb0 + 8u;
    const uint32_t STB = GSTW * 4u;

    float acc[4][4][4];
#pragma unroll
    for (int mt = 0; mt < 4; mt++)
#pragma unroll
        for (int nt = 0; nt < 4; nt++)
#pragma unroll
            for (int u = 0; u < 4; u++) acc[mt][nt][u] = 0.f;

    if (tid == 0) { mbar_init(mb0, 1); mbar_init(mb1, 1); }
    fence_async_init();
    __syncthreads();

    auto issue = [&](int ss, int kt) {
        const uint32_t base = sbase + (uint32_t)ss * GSTW * 4u;
        const uint32_t mb = ss ? mb1 : mb0;
        if (tid < 4) {
            const __nv_bfloat16* src;
            size_t off;
            if (tid < 2) {
                src = tid ? Al : Ah;
                off = ((size_t)kt * AR + arow0 + bm) * RSTR;
            } else {
                src = (tid == 2) ? Bh : Bl;
                off = ((size_t)kt * BR + brow0 + bn) * RSTR;
            }
            bulk_g2s(base + (uint32_t)tid * MATW * 4u, src + off, MATW * 4u, mb);
        }
    };

    if (tid == 0) mbar_expect(mb0, STB);
    __syncthreads();
    issue(0, 0);

#pragma unroll 2
    for (int kt = 0; kt < NKT; kt++) {
        const int s = kt & 1;
        if (kt < NKT - 1) {
            if (tid == 0) mbar_expect(s ? mb0 : mb1, STB);
            __syncthreads();
            issue(s ^ 1, kt + 1);
        }
        mbar_wait(s ? mb1 : mb0, (uint32_t)((kt >> 1) & 1));

        const uint32_t* Sw  = smem + s * GSTW;
        const uint32_t* AhW = Sw;
        const uint32_t* AlW = Sw + MATW;
        const uint32_t* BhW = Sw + 2 * MATW;
        const uint32_t* BlW = Sw + 3 * MATW;

#pragma unroll
        for (int ks = 0; ks < 2; ks++) {
            uint32_t bhf[4][2], blf[4][2];
#pragma unroll
            for (int nt = 0; nt < 4; nt++) {
                int wb = (n0 + nt * 8 + g) * (RSTR / 2) + ks * 8 + t;
                bhf[nt][0] = BhW[wb]; bhf[nt][1] = BhW[wb + 4];
                blf[nt][0] = BlW[wb]; blf[nt][1] = BlW[wb + 4];
            }
#pragma unroll
            for (int mt = 0; mt < 4; mt++) {
                int wa = (m0 + mt * 16 + g) * (RSTR / 2) + ks * 8 + t;
                uint32_t ah0 = AhW[wa],     ah1 = AhW[wa + 8 * (RSTR / 2)];
                uint32_t ah2 = AhW[wa + 4], ah3 = AhW[wa + 8 * (RSTR / 2) + 4];
                uint32_t al0 = AlW[wa],     al1 = AlW[wa + 8 * (RSTR / 2)];
                uint32_t al2 = AlW[wa + 4], al3 = AlW[wa + 8 * (RSTR / 2) + 4];
#pragma unroll
                for (int nt = 0; nt < 4; nt++) {
                    mma_bf16(acc[mt][nt], ah0, ah1, ah2, ah3, bhf[nt][0], bhf[nt][1]);
                    mma_bf16(acc[mt][nt], ah0, ah1, ah2, ah3, blf[nt][0], blf[nt][1]);
                    mma_bf16(acc[mt][nt], al0, al1, al2, al3, bhf[nt][0], bhf[nt][1]);
                }
            }
        }
    }

    // epilogue
#pragma unroll
    for (int mt = 0; mt < 4; mt++) {
#pragma unroll
        for (int nt = 0; nt < 4; nt++) {
            int r = bm + m0 + mt * 16 + g;
            int c = bn + n0 + nt * 8 + 2 * t;
            float bx = bias[c], by = bias[c + 1];
            float2 v0 = make_float2(acc[mt][nt][0] + bx, acc[mt][nt][1] + by);
            float2 v1 = make_float2(acc[mt][nt][2] + bx, acc[mt][nt][3] + by);
            if (mode == 0) {
                float* C = (float*)Cout;
                *(float2*)(C + (size_t)r * HDIM + c) = v0;
                *(float2*)(C + (size_t)(r + 8) * HDIM + c) = v1;
            } else if (mode == 1) {
                int b_ = r >> 10, sr = r & 1023, h_ = c >> 6, d0 = c & 63;
                __half* base = (__half*)Cout +
                    ((size_t)(b_ * NHEAD + h_) * SEQ + sr) * PADKH + d0;
                *(__half2*)base = __floats2half2_rn(v0.x, v0.y);
                *(__half2*)(base + (size_t)8 * PADKH) = __floats2half2_rn(v1.x, v1.y);
            } else {
                int b_ = r >> 10, sr = r & 1023, h_ = c >> 6;
                int kb = sr >> 5, kin = sr & 31, d0 = c & 63;
                __half* base = (__half*)Cout +
                    (((size_t)(b_ * NHEAD + h_) * (SEQ / KB) + kb) * DHEAD) * PADVTH;
                base[(size_t)d0 * PADVTH + kin]           = __float2half_rn(v0.x);
                base[(size_t)(d0 + 1) * PADVTH + kin]     = __float2half_rn(v0.y);
                base[(size_t)d0 * PADVTH + kin + 8]       = __float2half_rn(v1.x);
                base[(size_t)(d0 + 1) * PADVTH + kin + 8] = __float2half_rn(v1.y);
            }
        }
    }
}

__global__ void __launch_bounds__(256, 2)
qkv_gemm_kernel(const float* __restrict__ ipb)
{
    extern __shared__ uint32_t smem_g[];
    const int z = blockIdx.z;
    void* outp = (z == 0) ? (void*)g_q : (z == 1) ? (void*)g_kh : (void*)g_vth;
    gemm_core(g_inh, g_inl, AIR, z * ROWS,
              g_wh, g_wl, WR, z * HDIM,
              ipb + z * HDIM, outp, z, smem_g);
}

__global__ void __launch_bounds__(256, 2)
outproj_kernel(const float* __restrict__ outb, float* __restrict__ out)
{
    extern __shared__ uint32_t smem_g[];
    gemm_core(g_ah, g_al, ROWS, 0,
              g_wh, g_wl, WR, 3 * HDIM,
              outb, out, 0, smem_g);
}

// ============================================================================
// fp16 flash attention, bulk 2-stage; kb loop unrolled x2; no exp-guard.
// ============================================================================
#define QB 128
#define PADB 132
#define PADM 40
#define ST_V 4608
#define ST_B (ST_V + 5120)
#define ST_M (ST_B + KB*PADB*4)
#define ST_BYTES (ST_M + QB*PADM*4)
#define ATTN_TX (4608 + 5120 + KB*512 + QB*128)
#define ATTN_SMEM (2 * ST_BYTES + 16)

__device__ __forceinline__ void mma_f16(float c[4],
    uint32_t a0, uint32_t a1, uint32_t a2, uint32_t a3,
    uint32_t b0, uint32_t b1)
{
    asm volatile(
        "mma.sync.aligned.m16n8k16.row.col.f32.f16.f16.f32 "
        "{%0,%1,%2,%3}, {%4,%5,%6,%7}, {%8,%9}, {%0,%1,%2,%3};"
        : "+f"(c[0]), "+f"(c[1]), "+f"(c[2]), "+f"(c[3])
        : "r"(a0), "r"(a1), "r"(a2), "r"(a3), "r"(b0), "r"(b1));
}

__device__ __forceinline__ uint32_t packh2(float x, float y) {
    __half2 h = __floats2half2_rn(x, y);
    return *(uint32_t*)&h;
}

__global__ void __launch_bounds__(256, 2)
attn_mma_kernel(const float* __restrict__ kern,
                const uint32_t* __restrict__ amask, float scale)
{
    extern __shared__ char smc[];
    const uint32_t sbase = (uint32_t)__cvta_generic_to_shared(smc);
    const uint32_t mb0 = sbase + 2u * ST_BYTES;
    const uint32_t mb1 = mb0 + 8u;

    const int bh = blockIdx.y, b = bh >> 3, h = bh & 7;
    const int qb = blockIdx.x * QB;
    const int tid  = threadIdx.x;
    const int w    = tid >> 5;
    const int lane = tid & 31;
    const int g = lane >> 2, t = lane & 3;

    const int m_  = lane >> 3, r_ = lane & 7;
    const int flo = m_ >> 1, hh = m_ & 1;
    const uint32_t klane = (uint32_t)((flo * 8 + r_) * (PADKH * 2) + hh * 16);
    const uint32_t vlane = (uint32_t)((flo * 8 + r_) * (PADVTH * 2) + hh * 16);

    const float*  Qg = g_q + (size_t)b * SEQ * HDIM + h * DHEAD;
    const __half* Kp = g_kh + (size_t)bh * SEQ * PADKH;
    const __half* Vt = g_vth + (size_t)bh * (SEQ / KB) * DHEAD * PADVTH;
    const float* kern_bh = kern + (size_t)bh * SEQ * SEQ;
    const uint32_t* mask_bh = amask + (size_t)bh * SEQ * SEQ;

    if (tid == 0) { mbar_init(mb0, 1); mbar_init(mb1, 1); }
    fence_async_init();
    __syncthreads();

    auto issue = [&](int ss, int kb) {
        const uint32_t base = sbase + (uint32_t)ss * ST_BYTES;
        const uint32_t mb = ss ? mb1 : mb0;
        if (tid == 0)
            bulk_g2s(base, Kp + (size_t)kb * KB * PADKH, 4608u, mb);
        else if (tid == 1)
            bulk_g2s(base + ST_V, Vt + (size_t)kb * DHEAD * PADVTH, 5120u, mb);
        else if (tid >= 32 && tid < 64) {
            int r = tid - 32;
            bulk_g2s(base + (uint32_t)(ST_B + r * PADB * 4),
                     kern_bh + (size_t)(kb * KB + r) * SEQ + qb, 512u, mb);
        } else if (tid >= 64 && tid < 192) {
            int r = tid - 64;
            bulk_g2s(base + (uint32_t)(ST_M + r * PADM * 4),
                     mask_bh + (size_t)(qb + r) * SEQ + kb * KB, 128u, mb);
        }
    };

    if (tid == 0) mbar_expect(mb0, ATTN_TX);
    __syncthreads();
    issue(0, 0);

    // Q fragments, pre-scaled (exact: 2^-3)
    uint32_t qa[4][4];
    {
        const float* Qr0 = Qg + (size_t)(qb + w * 16 + g) * HDIM;
        const float* Qr1 = Qr0 + 8 * (size_t)HDIM;
#pragma unroll
        for (int kk = 0; kk < 4; kk++) {
            int d0 = 16 * kk + 2 * t;
            float2 x0 = *(const float2*)(Qr0 + d0);
            float2 x1 = *(const float2*)(Qr1 + d0);
            float2 x2 = *(const float2*)(Qr0 + d0 + 8);
            float2 x3 = *(const float2*)(Qr1 + d0 + 8);
            qa[kk][0] = packh2(x0.x * scale, x0.y * scale);
            qa[kk][1] = packh2(x1.x * scale, x1.y * scale);
            qa[kk][2] = packh2(x2.x * scale, x2.y * scale);
            qa[kk][3] = packh2(x3.x * scale, x3.y * scale);
        }
    }

    float o[8][4];
#pragma unroll
    for (int f = 0; f < 8; f++)
#pragma unroll
        for (int u = 0; u < 4; u++) o[f][u] = 0.f;
    float m_run[2] = {-1e30f, -1e30f}, l_run[2] = {0.f, 0.f};

    const int qrl0 = w * 16 + g;

    const int NT = SEQ / KB;
#pragma unroll 2
    for (int kb = 0; kb < NT; kb++) {
        const int s = kb & 1;
        if (kb < NT - 1) {
            if (tid == 0) mbar_expect(s ? mb0 : mb1, ATTN_TX);
            __syncthreads();
            issue(s ^ 1, kb + 1);
        }
        mbar_wait(s ? mb1 : mb0, (uint32_t)((kb >> 1) & 1));

        const char* Sb = smc + (size_t)s * ST_BYTES;
        const uint32_t stg = sbase + (uint32_t)s * ST_BYTES;
        const float*  Bs = (const float*)(Sb + ST_B);
        const uint32_t* Ms = (const uint32_t*)(Sb + ST_M);

        // ---- S accumulators initialized with the bias tile ----
        float sc[4][4];
#pragma unroll
        for (int f = 0; f < 4; f++) {
            int kc = f * 8 + 2 * t;
            sc[f][0] = Bs[kc * PADB + qrl0];
            sc[f][1] = Bs[(kc + 1) * PADB + qrl0];
            sc[f][2] = Bs[kc * PADB + qrl0 + 8];
            sc[f][3] = Bs[(kc + 1) * PADB + qrl0 + 8];
        }

        // ---- S += (scale*Q) K^T : LDSM.x4 fragments ----
#pragma unroll
        for (int kk = 0; kk < 4; kk++) {
#pragma unroll
            for (int j = 0; j < 2; j++) {
                uint32_t b00, b01, b10, b11;
                ldsm4(b00, b01, b10, b11,
                      stg + klane + (uint32_t)(j * 16 * PADKH * 2 + kk * 32));
                mma_f16(sc[2 * j],     qa[kk][0], qa[kk][1], qa[kk][2], qa[kk][3], b00, b01);
                mma_f16(sc[2 * j + 1], qa[kk][0], qa[kk][1], qa[kk][2], qa[kk][3], b10, b11);
            }
        }

        // ---- mask + online softmax (no exp guard: -1e30 underflows to 0) ----
#pragma unroll
        for (int e = 0; e < 2; e++) {
            const int qrl = qrl0 + e * 8;
            const uint2* Mrow = (const uint2*)(Ms + qrl * PADM);
            float rmax = -1e30f;
#pragma unroll
            for (int f = 0; f < 4; f++) {
                uint2 mw = Mrow[f * 4 + t];
                float s0 = sc[f][e * 2 + 0];
                float s1 = sc[f][e * 2 + 1];
                s0 = mw.x ? -1e30f : s0;
                s1 = mw.y ? -1e30f : s1;
                sc[f][e * 2 + 0] = s0;
                sc[f][e * 2 + 1] = s1;
                rmax = fmaxf(rmax, fmaxf(s0, s1));
            }
            rmax = fmaxf(rmax, __shfl_xor_sync(0xffffffffu, rmax, 1));
            rmax = fmaxf(rmax, __shfl_xor_sync(0xffffffffu, rmax, 2));
            float mn = fmaxf(m_run[e], rmax);
            float fe = __expf(m_run[e] - mn);
            float ps = 0.f;
#pragma unroll
            for (int f = 0; f < 4; f++) {
#pragma unroll
                for (int u = 0; u < 2; u++) {
                    float p = __expf(sc[f][e * 2 + u] - mn);
                    sc[f][e * 2 + u] = p;
                    ps += p;
                }
            }
            ps += __shfl_xor_sync(0xffffffffu, ps, 1);
            ps += __shfl_xor_sync(0xffffffffu, ps, 2);
            l_run[e] = l_run[e] * fe + ps;
            m_run[e] = mn;
#pragma unroll
            for (int f = 0; f < 4; f++) {
                o[2 * f][e * 2 + 0] *= fe;     o[2 * f][e * 2 + 1] *= fe;
                o[2 * f + 1][e * 2 + 0] *= fe; o[2 * f + 1][e * 2 + 1] *= fe;
            }
        }

        // ---- O += P @ V ----
#pragma unroll
        for (int kk = 0; kk < 2; kk++) {
            uint32_t a0 = packh2(sc[2 * kk][0],     sc[2 * kk][1]);
            uint32_t a1 = packh2(sc[2 * kk][2],     sc[2 * kk][3]);
            uint32_t a2 = packh2(sc[2 * kk + 1][0], sc[2 * kk + 1][1]);
            uint32_t a3 = packh2(sc[2 * kk + 1][2], sc[2 * kk + 1][3]);
#pragma unroll
            for (int j = 0; j < 4; j++) {
                uint32_t v00, v01, v10, v11;
                ldsm4(v00, v01, v10, v11,
                      stg + (uint32_t)ST_V + vlane +
                      (uint32_t)(j * 16 * PADVTH * 2 + kk * 32));
                mma_f16(o[2 * j],     a0, a1, a2, a3, v00, v01);
                mma_f16(o[2 * j + 1], a0, a1, a2, a3, v10, v11);
            }
        }
    }

    // ---- normalize + write hi/lo bf16 in outproj's tiled layout ----
#pragma unroll
    for (int e = 0; e < 2; e++) {
        float inv = 1.0f / l_run[e];
        int qrl = qrl0 + e * 8;
        size_t grow = (size_t)b * SEQ + qb + qrl;
#pragma unroll
        for (int f = 0; f < 8; f++) {
            float x = o[f][e * 2 + 0] * inv;
            float y = o[f][e * 2 + 1] * inv;
            __nv_bfloat16 hx = __float2bfloat16_rn(x);
            __nv_bfloat16 hy = __float2bfloat16_rn(y);
            __nv_bfloat16 lx = __float2bfloat16_rn(x - __bfloat162float(hx));
            __nv_bfloat16 ly = __float2bfloat16_rn(y - __bfloat162float(hy));
            __nv_bfloat162 hp(hx, hy), lp(lx, ly);
            int c = h * DHEAD + f * 8 + 2 * t;
            int kt = c >> 5, km = c & 31;
            size_t off = ((size_t)kt * ROWS + grow) * RSTR + km;
            *(uint32_t*)(g_ah + off) = *(uint32_t*)&hp;
            *(uint32_t*)(g_al + off) = *(uint32_t*)&lp;
        }
    }
}

// ============================================================================
// Launch
// ============================================================================
extern "C" void kernel_launch(void* const* d_in, const int* in_sizes, int n_in,
                              void* d_out, int out_size)
{
    const float* query    = (const float*)d_in[0];
    const float* key_     = (const float*)d_in[1];
    const float* value    = (const float*)d_in[2];
    const uint32_t* amask = (const uint32_t*)d_in[3];
    const float* kern     = (const float*)d_in[5];
    const float* ipw      = (const float*)d_in[6];
    const float* ipb      = (const float*)d_in[7];
    const float* outw     = (const float*)d_in[8];
    const float* outb     = (const float*)d_in[9];
    float* out = (float*)d_out;

    cudaFuncSetAttribute(attn_mma_kernel,
                         cudaFuncAttributeMaxDynamicSharedMemorySize, ATTN_SMEM);
    cudaFuncSetAttribute(qkv_gemm_kernel,
                         cudaFuncAttributeMaxDynamicSharedMemorySize, GEMM_SMEM);
    cudaFuncSetAttribute(outproj_kernel,
                         cudaFuncAttributeMaxDynamicSharedMemorySize, GEMM_SMEM);

    split_in_kernel<<<3 * ROWS * 64 / 256, 256>>>(query, key_, value);
    split_w_kernel<<<WR * 64 / 256, 256>>>(ipw, outw);

    dim3 gq(HDIM / TBN, ROWS / TBM, 3);
    qkv_gemm_kernel<<<gq, 256, GEMM_SMEM>>>(ipb);

    dim3 ga(SEQ / QB, BATCH * NHEAD, 1);
    attn_mma_kernel<<<ga, 256, ATTN_SMEM>>>(kern, amask, 0.125f);

    dim3 go(HDIM / TBN, ROWS / TBM, 1);
    outproj_kernel<<<go, 256, GEMM_SMEM>>>(outb, out);
}

// round 14
// speedup vs baseline: 1.4115x; 1.4115x over previous
#include <cuda_runtime.h>
#include <cuda_bf16.h>
#include <cuda_fp16.h>
#include <cstdint>

// ----------------------------------------------------------------------------
// PositionAttention: B=4, L=1024, HD=512, H=8, D=64
// Round 14: revert R13's unroll pragmas (regression: I-cache/body bloat).
// Keep only the exp-guard removal (numerics-identical, validated in R13).
// Structure == R12 otherwise.
// ----------------------------------------------------------------------------

#define BATCH 4
#define SEQ   1024
#define HDIM  512
#define NHEAD 8
#define DHEAD 64
#define ROWS  (BATCH*SEQ)          // 4096

#define RSTR 40
#define NKT  (HDIM/32)
#define AIR  (3*ROWS)
#define WR   2048

#define KB    32
#define PADKH 72
#define PADVTH 40

__device__ __align__(16) float  g_q[ROWS * HDIM];
__device__ __align__(16) __half g_kh[(size_t)BATCH*NHEAD*SEQ*PADKH];
__device__ __align__(16) __half g_vth[(size_t)BATCH*NHEAD*(SEQ/KB)*DHEAD*PADVTH];
__device__ __align__(16) __nv_bfloat16 g_inh[(size_t)NKT*AIR*RSTR];
__device__ __align__(16) __nv_bfloat16 g_inl[(size_t)NKT*AIR*RSTR];
__device__ __align__(16) __nv_bfloat16 g_wh[(size_t)NKT*WR*RSTR];
__device__ __align__(16) __nv_bfloat16 g_wl[(size_t)NKT*WR*RSTR];
__device__ __align__(16) __nv_bfloat16 g_ah[(size_t)NKT*ROWS*RSTR];
__device__ __align__(16) __nv_bfloat16 g_al[(size_t)NKT*ROWS*RSTR];

// ============================================================================
// mbarrier / bulk-copy primitives
// ============================================================================
__device__ __forceinline__ void mbar_init(uint32_t a, uint32_t cnt) {
    asm volatile("mbarrier.init.shared.b64 [%0], %1;" :: "r"(a), "r"(cnt) : "memory");
}
__device__ __forceinline__ void mbar_expect(uint32_t a, uint32_t bytes) {
    asm volatile("mbarrier.arrive.expect_tx.shared.b64 _, [%0], %1;"
                 :: "r"(a), "r"(bytes) : "memory");
}
__device__ __forceinline__ void mbar_wait(uint32_t a, uint32_t parity) {
    asm volatile(
        "{\n\t.reg .pred P;\n\t"
        "WAIT_%=:\n\t"
        "mbarrier.try_wait.parity.acquire.cta.shared::cta.b64 P, [%0], %1, 0x989680;\n\t"
        "@P bra.uni DONE_%=;\n\t"
        "bra.uni WAIT_%=;\n\t"
        "DONE_%=:\n\t}"
        :: "r"(a), "r"(parity) : "memory");
}
__device__ __forceinline__ void bulk_g2s(uint32_t dst, const void* src,
                                         uint32_t bytes, uint32_t mbar) {
    asm volatile(
        "cp.async.bulk.shared::cta.global.mbarrier::complete_tx::bytes "
        "[%0], [%1], %2, [%3];"
        :: "r"(dst), "l"(src), "r"(bytes), "r"(mbar) : "memory");
}
__device__ __forceinline__ void fence_async_init() {
    asm volatile("fence.proxy.async.shared::cta;" ::: "memory");
}
__device__ __forceinline__ void ldsm4(uint32_t& r0, uint32_t& r1,
                                      uint32_t& r2, uint32_t& r3, uint32_t addr) {
    asm volatile("ldmatrix.sync.aligned.m8n8.x4.shared.b16 {%0,%1,%2,%3}, [%4];"
                 : "=r"(r0), "=r"(r1), "=r"(r2), "=r"(r3) : "r"(addr));
}

// ============================================================================
// split kernels (unchanged)
// ============================================================================
__device__ __forceinline__ void split8(const float* src, uint4& hw, uint4& lw)
{
    float4 a = *(const float4*)src;
    float4 b = *(const float4*)(src + 4);
    float v[8] = {a.x, a.y, a.z, a.w, b.x, b.y, b.z, b.w};
    uint32_t h[4], l[4];
#pragma unroll
    for (int i = 0; i < 4; i++) {
        __nv_bfloat16 h0 = __float2bfloat16_rn(v[2*i]);
        __nv_bfloat16 h1 = __float2bfloat16_rn(v[2*i+1]);
        __nv_bfloat16 l0 = __float2bfloat16_rn(v[2*i]   - __bfloat162float(h0));
        __nv_bfloat16 l1 = __float2bfloat16_rn(v[2*i+1] - __bfloat162float(h1));
        __nv_bfloat162 hp(h0, h1), lp(l0, l1);
        h[i] = *(uint32_t*)&hp; l[i] = *(uint32_t*)&lp;
    }
    hw = make_uint4(h[0], h[1], h[2], h[3]);
    lw = make_uint4(l[0], l[1], l[2], l[3]);
}

__global__ void __launch_bounds__(256)
split_in_kernel(const float* __restrict__ q, const float* __restrict__ k,
                const float* __restrict__ v)
{
    size_t i = (size_t)blockIdx.x * 256 + threadIdx.x;
    int mat = (int)(i / (ROWS * 64));
    size_t rem = i - (size_t)mat * (ROWS * 64);
    int r = (int)(rem >> 6);
    int kk = ((int)rem & 63) * 8;
    int kt = kk >> 5, km = kk & 31;
    const float* src = (mat == 0 ? q : mat == 1 ? k : v) + ((size_t)r << 9) + kk;
    uint4 hw, lw; split8(src, hw, lw);
    size_t d = ((size_t)kt * AIR + (size_t)mat * ROWS + r) * RSTR + km;
    *(uint4*)(g_inh + d) = hw;
    *(uint4*)(g_inl + d) = lw;
}

__global__ void __launch_bounds__(256)
split_w_kernel(const float* __restrict__ ipw, const float* __restrict__ outw)
{
    size_t i = (size_t)blockIdx.x * 256 + threadIdx.x;
    int r = (int)(i >> 6);
    int kk = ((int)i & 63) * 8;
    int kt = kk >> 5, km = kk & 31;
    const float* src = (r < 1536) ? (ipw + ((size_t)r << 9) + kk)
                                  : (outw + ((size_t)(r - 1536) << 9) + kk);
    uint4 hw, lw; split8(src, hw, lw);
    size_t d = ((size_t)kt * WR + r) * RSTR + km;
    *(uint4*)(g_wh + d) = hw;
    *(uint4*)(g_wl + d) = lw;
}

// ============================================================================
// bf16x3 GEMM, bulk 2-stage (R12 structure, no unroll pragma).
// ============================================================================
#define TBM 128
#define TBN 128
#define MATW (TBM * RSTR / 2)
#define GSTW (4 * MATW)
#define GEMM_SMEM (2 * GSTW * 4 + 16)

__device__ __forceinline__ void mma_bf16(float c[4],
    uint32_t a0, uint32_t a1, uint32_t a2, uint32_t a3,
    uint32_t b0, uint32_t b1)
{
    asm volatile(
        "mma.sync.aligned.m16n8k16.row.col.f32.bf16.bf16.f32 "
        "{%0,%1,%2,%3}, {%4,%5,%6,%7}, {%8,%9}, {%0,%1,%2,%3};"
        : "+f"(c[0]), "+f"(c[1]), "+f"(c[2]), "+f"(c[3])
        : "r"(a0), "r"(a1), "r"(a2), "r"(a3), "r"(b0), "r"(b1));
}

__device__ __forceinline__ void gemm_core(
    const __nv_bfloat16* __restrict__ Ah, const __nv_bfloat16* __restrict__ Al,
    int AR, int arow0,
    const __nv_bfloat16* __restrict__ Bh, const __nv_bfloat16* __restrict__ Bl,
    int BR, int brow0,
    const float* __restrict__ bias, void* __restrict__ Cout, int mode,
    uint32_t* smem)
{
    const int tid  = threadIdx.x;
    const int w    = tid >> 5;
    const int lane = tid & 31;
    const int g = lane >> 2, t = lane & 3;
    const int wm = w >> 2, wn = w & 3;
    const int m0 = wm * 64, n0 = wn * 32;
    const int bm = blockIdx.y * TBM;
    const int bn = blockIdx.x * TBN;
    const uint32_t sbase = (uint32_t)__cvta_generic_to_shared(smem);
    const uint32_t mb0 = sbase + 2u * GSTW * 4u;
    const uint32_t mb1 = mb0 + 8u;
    const uint32_t STB = GSTW * 4u;

    float acc[4][4][4];
#pragma unroll
    for (int mt = 0; mt < 4; mt++)
#pragma unroll
        for (int nt = 0; nt < 4; nt++)
#pragma unroll
            for (int u = 0; u < 4; u++) acc[mt][nt][u] = 0.f;

    if (tid == 0) { mbar_init(mb0, 1); mbar_init(mb1, 1); }
    fence_async_init();
    __syncthreads();

    auto issue = [&](int ss, int kt) {
        const uint32_t base = sbase + (uint32_t)ss * GSTW * 4u;
        const uint32_t mb = ss ? mb1 : mb0;
        if (tid < 4) {
            const __nv_bfloat16* src;
            size_t off;
            if (tid < 2) {
                src = tid ? Al : Ah;
                off = ((size_t)kt * AR + arow0 + bm) * RSTR;
            } else {
                src = (tid == 2) ? Bh : Bl;
                off = ((size_t)kt * BR + brow0 + bn) * RSTR;
            }
            bulk_g2s(base + (uint32_t)tid * MATW * 4u, src + off, MATW * 4u, mb);
        }
    };

    if (tid == 0) mbar_expect(mb0, STB);
    __syncthreads();
    issue(0, 0);

    for (int kt = 0; kt < NKT; kt++) {
        const int s = kt & 1;
        if (kt < NKT - 1) {
            if (tid == 0) mbar_expect(s ? mb0 : mb1, STB);
            __syncthreads();
            issue(s ^ 1, kt + 1);
        }
        mbar_wait(s ? mb1 : mb0, (uint32_t)((kt >> 1) & 1));

        const uint32_t* Sw  = smem + s * GSTW;
        const uint32_t* AhW = Sw;
        const uint32_t* AlW = Sw + MATW;
        const uint32_t* BhW = Sw + 2 * MATW;
        const uint32_t* BlW = Sw + 3 * MATW;

#pragma unroll
        for (int ks = 0; ks < 2; ks++) {
            uint32_t bhf[4][2], blf[4][2];
#pragma unroll
            for (int nt = 0; nt < 4; nt++) {
                int wb = (n0 + nt * 8 + g) * (RSTR / 2) + ks * 8 + t;
                bhf[nt][0] = BhW[wb]; bhf[nt][1] = BhW[wb + 4];
                blf[nt][0] = BlW[wb]; blf[nt][1] = BlW[wb + 4];
            }
#pragma unroll
            for (int mt = 0; mt < 4; mt++) {
                int wa = (m0 + mt * 16 + g) * (RSTR / 2) + ks * 8 + t;
                uint32_t ah0 = AhW[wa],     ah1 = AhW[wa + 8 * (RSTR / 2)];
                uint32_t ah2 = AhW[wa + 4], ah3 = AhW[wa + 8 * (RSTR / 2) + 4];
                uint32_t al0 = AlW[wa],     al1 = AlW[wa + 8 * (RSTR / 2)];
                uint32_t al2 = AlW[wa + 4], al3 = AlW[wa + 8 * (RSTR / 2) + 4];
#pragma unroll
                for (int nt = 0; nt < 4; nt++) {
                    mma_bf16(acc[mt][nt], ah0, ah1, ah2, ah3, bhf[nt][0], bhf[nt][1]);
                    mma_bf16(acc[mt][nt], ah0, ah1, ah2, ah3, blf[nt][0], blf[nt][1]);
                    mma_bf16(acc[mt][nt], al0, al1, al2, al3, bhf[nt][0], bhf[nt][1]);
                }
            }
        }
    }

    // epilogue
#pragma unroll
    for (int mt = 0; mt < 4; mt++) {
#pragma unroll
        for (int nt = 0; nt < 4; nt++) {
            int r = bm + m0 + mt * 16 + g;
            int c = bn + n0 + nt * 8 + 2 * t;
            float bx = bias[c], by = bias[c + 1];
            float2 v0 = make_float2(acc[mt][nt][0] + bx, acc[mt][nt][1] + by);
            float2 v1 = make_float2(acc[mt][nt][2] + bx, acc[mt][nt][3] + by);
            if (mode == 0) {
                float* C = (float*)Cout;
                *(float2*)(C + (size_t)r * HDIM + c) = v0;
                *(float2*)(C + (size_t)(r + 8) * HDIM + c) = v1;
            } else if (mode == 1) {
                int b_ = r >> 10, sr = r & 1023, h_ = c >> 6, d0 = c & 63;
                __half* base = (__half*)Cout +
                    ((size_t)(b_ * NHEAD + h_) * SEQ + sr) * PADKH + d0;
                *(__half2*)base = __floats2half2_rn(v0.x, v0.y);
                *(__half2*)(base + (size_t)8 * PADKH) = __floats2half2_rn(v1.x, v1.y);
            } else {
                int b_ = r >> 10, sr = r & 1023, h_ = c >> 6;
                int kb = sr >> 5, kin = sr & 31, d0 = c & 63;
                __half* base = (__half*)Cout +
                    (((size_t)(b_ * NHEAD + h_) * (SEQ / KB) + kb) * DHEAD) * PADVTH;
                base[(size_t)d0 * PADVTH + kin]           = __float2half_rn(v0.x);
                base[(size_t)(d0 + 1) * PADVTH + kin]     = __float2half_rn(v0.y);
                base[(size_t)d0 * PADVTH + kin + 8]       = __float2half_rn(v1.x);
                base[(size_t)(d0 + 1) * PADVTH + kin + 8] = __float2half_rn(v1.y);
            }
        }
    }
}

__global__ void __launch_bounds__(256, 2)
qkv_gemm_kernel(const float* __restrict__ ipb)
{
    extern __shared__ uint32_t smem_g[];
    const int z = blockIdx.z;
    void* outp = (z == 0) ? (void*)g_q : (z == 1) ? (void*)g_kh : (void*)g_vth;
    gemm_core(g_inh, g_inl, AIR, z * ROWS,
              g_wh, g_wl, WR, z * HDIM,
              ipb + z * HDIM, outp, z, smem_g);
}

__global__ void __launch_bounds__(256, 2)
outproj_kernel(const float* __restrict__ outb, float* __restrict__ out)
{
    extern __shared__ uint32_t smem_g[];
    gemm_core(g_ah, g_al, ROWS, 0,
              g_wh, g_wl, WR, 3 * HDIM,
              outb, out, 0, smem_g);
}

// ============================================================================
// fp16 flash attention, bulk 2-stage (R12 structure); no exp-guard.
// ============================================================================
#define QB 128
#define PADB 132
#define PADM 40
#define ST_V 4608
#define ST_B (ST_V + 5120)
#define ST_M (ST_B + KB*PADB*4)
#define ST_BYTES (ST_M + QB*PADM*4)
#define ATTN_TX (4608 + 5120 + KB*512 + QB*128)
#define ATTN_SMEM (2 * ST_BYTES + 16)

__device__ __forceinline__ void mma_f16(float c[4],
    uint32_t a0, uint32_t a1, uint32_t a2, uint32_t a3,
    uint32_t b0, uint32_t b1)
{
    asm volatile(
        "mma.sync.aligned.m16n8k16.row.col.f32.f16.f16.f32 "
        "{%0,%1,%2,%3}, {%4,%5,%6,%7}, {%8,%9}, {%0,%1,%2,%3};"
        : "+f"(c[0]), "+f"(c[1]), "+f"(c[2]), "+f"(c[3])
        : "r"(a0), "r"(a1), "r"(a2), "r"(a3), "r"(b0), "r"(b1));
}

__device__ __forceinline__ uint32_t packh2(float x, float y) {
    __half2 h = __floats2half2_rn(x, y);
    return *(uint32_t*)&h;
}

__global__ void __launch_bounds__(256, 2)
attn_mma_kernel(const float* __restrict__ kern,
                const uint32_t* __restrict__ amask, float scale)
{
    extern __shared__ char smc[];
    const uint32_t sbase = (uint32_t)__cvta_generic_to_shared(smc);
    const uint32_t mb0 = sbase + 2u * ST_BYTES;
    const uint32_t mb1 = mb0 + 8u;

    const int bh = blockIdx.y, b = bh >> 3, h = bh & 7;
    const int qb = blockIdx.x * QB;
    const int tid  = threadIdx.x;
    const int w    = tid >> 5;
    const int lane = tid & 31;
    const int g = lane >> 2, t = lane & 3;

    const int m_  = lane >> 3, r_ = lane & 7;
    const int flo = m_ >> 1, hh = m_ & 1;
    const uint32_t klane = (uint32_t)((flo * 8 + r_) * (PADKH * 2) + hh * 16);
    const uint32_t vlane = (uint32_t)((flo * 8 + r_) * (PADVTH * 2) + hh * 16);

    const float*  Qg = g_q + (size_t)b * SEQ * HDIM + h * DHEAD;
    const __half* Kp = g_kh + (size_t)bh * SEQ * PADKH;
    const __half* Vt = g_vth + (size_t)bh * (SEQ / KB) * DHEAD * PADVTH;
    const float* kern_bh = kern + (size_t)bh * SEQ * SEQ;
    const uint32_t* mask_bh = amask + (size_t)bh * SEQ * SEQ;

    if (tid == 0) { mbar_init(mb0, 1); mbar_init(mb1, 1); }
    fence_async_init();
    __syncthreads();

    auto issue = [&](int ss, int kb) {
        const uint32_t base = sbase + (uint32_t)ss * ST_BYTES;
        const uint32_t mb = ss ? mb1 : mb0;
        if (tid == 0)
            bulk_g2s(base, Kp + (size_t)kb * KB * PADKH, 4608u, mb);
        else if (tid == 1)
            bulk_g2s(base + ST_V, Vt + (size_t)kb * DHEAD * PADVTH, 5120u, mb);
        else if (tid >= 32 && tid < 64) {
            int r = tid - 32;
            bulk_g2s(base + (uint32_t)(ST_B + r * PADB * 4),
                     kern_bh + (size_t)(kb * KB + r) * SEQ + qb, 512u, mb);
        } else if (tid >= 64 && tid < 192) {
            int r = tid - 64;
            bulk_g2s(base + (uint32_t)(ST_M + r * PADM * 4),
                     mask_bh + (size_t)(qb + r) * SEQ + kb * KB, 128u, mb);
        }
    };

    if (tid == 0) mbar_expect(mb0, ATTN_TX);
    __syncthreads();
    issue(0, 0);

    // Q fragments, pre-scaled (exact: 2^-3)
    uint32_t qa[4][4];
    {
        const float* Qr0 = Qg + (size_t)(qb + w * 16 + g) * HDIM;
        const float* Qr1 = Qr0 + 8 * (size_t)HDIM;
#pragma unroll
        for (int kk = 0; kk < 4; kk++) {
            int d0 = 16 * kk + 2 * t;
            float2 x0 = *(const float2*)(Qr0 + d0);
            float2 x1 = *(const float2*)(Qr1 + d0);
            float2 x2 = *(const float2*)(Qr0 + d0 + 8);
            float2 x3 = *(const float2*)(Qr1 + d0 + 8);
            qa[kk][0] = packh2(x0.x * scale, x0.y * scale);
            qa[kk][1] = packh2(x1.x * scale, x1.y * scale);
            qa[kk][2] = packh2(x2.x * scale, x2.y * scale);
            qa[kk][3] = packh2(x3.x * scale, x3.y * scale);
        }
    }

    float o[8][4];
#pragma unroll
    for (int f = 0; f < 8; f++)
#pragma unroll
        for (int u = 0; u < 4; u++) o[f][u] = 0.f;
    float m_run[2] = {-1e30f, -1e30f}, l_run[2] = {0.f, 0.f};

    const int qrl0 = w * 16 + g;

    const int NT = SEQ / KB;
    for (int kb = 0; kb < NT; kb++) {
        const int s = kb & 1;
        if (kb < NT - 1) {
            if (tid == 0) mbar_expect(s ? mb0 : mb1, ATTN_TX);
            __syncthreads();
            issue(s ^ 1, kb + 1);
        }
        mbar_wait(s ? mb1 : mb0, (uint32_t)((kb >> 1) & 1));

        const char* Sb = smc + (size_t)s * ST_BYTES;
        const uint32_t stg = sbase + (uint32_t)s * ST_BYTES;
        const float*  Bs = (const float*)(Sb + ST_B);
        const uint32_t* Ms = (const uint32_t*)(Sb + ST_M);

        // ---- S accumulators initialized with the bias tile ----
        float sc[4][4];
#pragma unroll
        for (int f = 0; f < 4; f++) {
            int kc = f * 8 + 2 * t;
            sc[f][0] = Bs[kc * PADB + qrl0];
            sc[f][1] = Bs[(kc + 1) * PADB + qrl0];
            sc[f][2] = Bs[kc * PADB + qrl0 + 8];
            sc[f][3] = Bs[(kc + 1) * PADB + qrl0 + 8];
        }

        // ---- S += (scale*Q) K^T : LDSM.x4 fragments ----
#pragma unroll
        for (int kk = 0; kk < 4; kk++) {
#pragma unroll
            for (int j = 0; j < 2; j++) {
                uint32_t b00, b01, b10, b11;
                ldsm4(b00, b01, b10, b11,
                      stg + klane + (uint32_t)(j * 16 * PADKH * 2 + kk * 32));
                mma_f16(sc[2 * j],     qa[kk][0], qa[kk][1], qa[kk][2], qa[kk][3], b00, b01);
                mma_f16(sc[2 * j + 1], qa[kk][0], qa[kk][1], qa[kk][2], qa[kk][3], b10, b11);
            }
        }

        // ---- mask + online softmax (no exp guard: -1e30 underflows to 0) ----
#pragma unroll
        for (int e = 0; e < 2; e++) {
            const int qrl = qrl0 + e * 8;
            const uint2* Mrow = (const uint2*)(Ms + qrl * PADM);
            float rmax = -1e30f;
#pragma unroll
            for (int f = 0; f < 4; f++) {
                uint2 mw = Mrow[f * 4 + t];
                float s0 = sc[f][e * 2 + 0];
                float s1 = sc[f][e * 2 + 1];
                s0 = mw.x ? -1e30f : s0;
                s1 = mw.y ? -1e30f : s1;
                sc[f][e * 2 + 0] = s0;
                sc[f][e * 2 + 1] = s1;
                rmax = fmaxf(rmax, fmaxf(s0, s1));
            }
            rmax = fmaxf(rmax, __shfl_xor_sync(0xffffffffu, rmax, 1));
            rmax = fmaxf(rmax, __shfl_xor_sync(0xffffffffu, rmax, 2));
            float mn = fmaxf(m_run[e], rmax);
            float fe = __expf(m_run[e] - mn);
            float ps = 0.f;
#pragma unroll
            for (int f = 0; f < 4; f++) {
#pragma unroll
                for (int u = 0; u < 2; u++) {
                    float p = __expf(sc[f][e * 2 + u] - mn);
                    sc[f][e * 2 + u] = p;
                    ps += p;
                }
            }
            ps += __shfl_xor_sync(0xffffffffu, ps, 1);
            ps += __shfl_xor_sync(0xffffffffu, ps, 2);
            l_run[e] = l_run[e] * fe + ps;
            m_run[e] = mn;
#pragma unroll
            for (int f = 0; f < 4; f++) {
                o[2 * f][e * 2 + 0] *= fe;     o[2 * f][e * 2 + 1] *= fe;
                o[2 * f + 1][e * 2 + 0] *= fe; o[2 * f + 1][e * 2 + 1] *= fe;
            }
        }

        // ---- O += P @ V ----
#pragma unroll
        for (int kk = 0; kk < 2; kk++) {
            uint32_t a0 = packh2(sc[2 * kk][0],     sc[2 * kk][1]);
            uint32_t a1 = packh2(sc[2 * kk][2],     sc[2 * kk][3]);
            uint32_t a2 = packh2(sc[2 * kk + 1][0], sc[2 * kk + 1][1]);
            uint32_t a3 = packh2(sc[2 * kk + 1][2], sc[2 * kk + 1][3]);
#pragma unroll
            for (int j = 0; j < 4; j++) {
                uint32_t v00, v01, v10, v11;
                ldsm4(v00, v01, v10, v11,
                      stg + (uint32_t)ST_V + vlane +
                      (uint32_t)(j * 16 * PADVTH * 2 + kk * 32));
                mma_f16(o[2 * j],     a0, a1, a2, a3, v00, v01);
                mma_f16(o[2 * j + 1], a0, a1, a2, a3, v10, v11);
            }
        }
    }

    // ---- normalize + write hi/lo bf16 in outproj's tiled layout ----
#pragma unroll
    for (int e = 0; e < 2; e++) {
        float inv = 1.0f / l_run[e];
        int qrl = qrl0 + e * 8;
        size_t grow = (size_t)b * SEQ + qb + qrl;
#pragma unroll
        for (int f = 0; f < 8; f++) {
            float x = o[f][e * 2 + 0] * inv;
            float y = o[f][e * 2 + 1] * inv;
            __nv_bfloat16 hx = __float2bfloat16_rn(x);
            __nv_bfloat16 hy = __float2bfloat16_rn(y);
            __nv_bfloat16 lx = __float2bfloat16_rn(x - __bfloat162float(hx));
            __nv_bfloat16 ly = __float2bfloat16_rn(y - __bfloat162float(hy));
            __nv_bfloat162 hp(hx, hy), lp(lx, ly);
            int c = h * DHEAD + f * 8 + 2 * t;
            int kt = c >> 5, km = c & 31;
            size_t off = ((size_t)kt * ROWS + grow) * RSTR + km;
            *(uint32_t*)(g_ah + off) = *(uint32_t*)&hp;
            *(uint32_t*)(g_al + off) = *(uint32_t*)&lp;
        }
    }
}

// ============================================================================
// Launch
// ============================================================================
extern "C" void kernel_launch(void* const* d_in, const int* in_sizes, int n_in,
                              void* d_out, int out_size)
{
    const float* query    = (const float*)d_in[0];
    const float* key_     = (const float*)d_in[1];
    const float* value    = (const float*)d_in[2];
    const uint32_t* amask = (const uint32_t*)d_in[3];
    const float* kern     = (const float*)d_in[5];
    const float* ipw      = (const float*)d_in[6];
    const float* ipb      = (const float*)d_in[7];
    const float* outw     = (const float*)d_in[8];
    const float* outb     = (const float*)d_in[9];
    float* out = (float*)d_out;

    cudaFuncSetAttribute(attn_mma_kernel,
                         cudaFuncAttributeMaxDynamicSharedMemorySize, ATTN_SMEM);
    cudaFuncSetAttribute(qkv_gemm_kernel,
                         cudaFuncAttributeMaxDynamicSharedMemorySize, GEMM_SMEM);
    cudaFuncSetAttribute(outproj_kernel,
                         cudaFuncAttributeMaxDynamicSharedMemorySize, GEMM_SMEM);

    split_in_kernel<<<3 * ROWS * 64 / 256, 256>>>(query, key_, value);
    split_w_kernel<<<WR * 64 / 256, 256>>>(ipw, outw);

    dim3 gq(HDIM / TBN, ROWS / TBM, 3);
    qkv_gemm_kernel<<<gq, 256, GEMM_SMEM>>>(ipb);

    dim3 ga(SEQ / QB, BATCH * NHEAD, 1);
    attn_mma_kernel<<<ga, 256, ATTN_SMEM>>>(kern, amask, 0.125f);

    dim3 go(HDIM / TBN, ROWS / TBM, 1);
    outproj_kernel<<<go, 256, GEMM_SMEM>>>(outb, out);
}

// round 16
// speedup vs baseline: 1.6490x; 1.1683x over previous
#include <cuda_runtime.h>
#include <cuda_bf16.h>
#include <cuda_fp16.h>
#include <cstdint>

// ----------------------------------------------------------------------------
// PositionAttention: B=4, L=1024, HD=512, H=8, D=64
// Round 16: R15 with the OOB fix — gemm_core's A staging used AIR instead of
// the AR parameter, overrunning g_af in outproj (illegal memory access).
// GEMMs: asymmetric fp16 split (A fp16, W hi/lo fp16, 2 MMAs/tile).
// Attention mainloop unchanged from R14 (165.95us best).
// ----------------------------------------------------------------------------

#define BATCH 4
#define SEQ   1024
#define HDIM  512
#define NHEAD 8
#define DHEAD 64
#define ROWS  (BATCH*SEQ)          // 4096

#define RSTR 40                    // fp16 per tiled row (32 data + 8 pad)
#define NKT  (HDIM/32)             // 16 k-tiles
#define AIR  (3*ROWS)
#define WR   2048                  // ipw 1536 rows + outw 512 rows

#define KB    32
#define PADKH 72
#define PADVTH 40

// scratch (allocation-free device globals)
__device__ __align__(16) float  g_q[ROWS * HDIM];
__device__ __align__(16) __half g_kh[(size_t)BATCH*NHEAD*SEQ*PADKH];
__device__ __align__(16) __half g_vth[(size_t)BATCH*NHEAD*(SEQ/KB)*DHEAD*PADVTH];
__device__ __align__(16) __half g_inf[(size_t)NKT*AIR*RSTR];   // inputs fp16, tiled
__device__ __align__(16) __half g_wh[(size_t)NKT*WR*RSTR];     // weights hi fp16
__device__ __align__(16) __half g_wl[(size_t)NKT*WR*RSTR];     // weights lo fp16
__device__ __align__(16) __half g_af[(size_t)NKT*ROWS*RSTR];   // attn out fp16, tiled

// ============================================================================
// mbarrier / bulk-copy primitives
// ============================================================================
__device__ __forceinline__ void mbar_init(uint32_t a, uint32_t cnt) {
    asm volatile("mbarrier.init.shared.b64 [%0], %1;" :: "r"(a), "r"(cnt) : "memory");
}
__device__ __forceinline__ void mbar_expect(uint32_t a, uint32_t bytes) {
    asm volatile("mbarrier.arrive.expect_tx.shared.b64 _, [%0], %1;"
                 :: "r"(a), "r"(bytes) : "memory");
}
__device__ __forceinline__ void mbar_wait(uint32_t a, uint32_t parity) {
    asm volatile(
        "{\n\t.reg .pred P;\n\t"
        "WAIT_%=:\n\t"
        "mbarrier.try_wait.parity.acquire.cta.shared::cta.b64 P, [%0], %1, 0x989680;\n\t"
        "@P bra.uni DONE_%=;\n\t"
        "bra.uni WAIT_%=;\n\t"
        "DONE_%=:\n\t}"
        :: "r"(a), "r"(parity) : "memory");
}
__device__ __forceinline__ void bulk_g2s(uint32_t dst, const void* src,
                                         uint32_t bytes, uint32_t mbar) {
    asm volatile(
        "cp.async.bulk.shared::cta.global.mbarrier::complete_tx::bytes "
        "[%0], [%1], %2, [%3];"
        :: "r"(dst), "l"(src), "r"(bytes), "r"(mbar) : "memory");
}
__device__ __forceinline__ void fence_async_init() {
    asm volatile("fence.proxy.async.shared::cta;" ::: "memory");
}
__device__ __forceinline__ void ldsm4(uint32_t& r0, uint32_t& r1,
                                      uint32_t& r2, uint32_t& r3, uint32_t addr) {
    asm volatile("ldmatrix.sync.aligned.m8n8.x4.shared.b16 {%0,%1,%2,%3}, [%4];"
                 : "=r"(r0), "=r"(r1), "=r"(r2), "=r"(r3) : "r"(addr));
}
__device__ __forceinline__ void mma_f16(float c[4],
    uint32_t a0, uint32_t a1, uint32_t a2, uint32_t a3,
    uint32_t b0, uint32_t b1)
{
    asm volatile(
        "mma.sync.aligned.m16n8k16.row.col.f32.f16.f16.f32 "
        "{%0,%1,%2,%3}, {%4,%5,%6,%7}, {%8,%9}, {%0,%1,%2,%3};"
        : "+f"(c[0]), "+f"(c[1]), "+f"(c[2]), "+f"(c[3])
        : "r"(a0), "r"(a1), "r"(a2), "r"(a3), "r"(b0), "r"(b1));
}
__device__ __forceinline__ uint32_t packh2(float x, float y) {
    __half2 h = __floats2half2_rn(x, y);
    return *(uint32_t*)&h;
}

// ============================================================================
// convert/split kernels
// ============================================================================
__global__ void __launch_bounds__(256)
convert_in_kernel(const float* __restrict__ q, const float* __restrict__ k,
                  const float* __restrict__ v)
{
    size_t i = (size_t)blockIdx.x * 256 + threadIdx.x;
    int mat = (int)(i / (ROWS * 64));
    size_t rem = i - (size_t)mat * (ROWS * 64);
    int r = (int)(rem >> 6);
    int kk = ((int)rem & 63) * 8;
    int kt = kk >> 5, km = kk & 31;
    const float* src = (mat == 0 ? q : mat == 1 ? k : v) + ((size_t)r << 9) + kk;
    float4 a = *(const float4*)src;
    float4 b = *(const float4*)(src + 4);
    uint4 hv;
    hv.x = packh2(a.x, a.y);
    hv.y = packh2(a.z, a.w);
    hv.z = packh2(b.x, b.y);
    hv.w = packh2(b.z, b.w);
    size_t d = ((size_t)kt * AIR + (size_t)mat * ROWS + r) * RSTR + km;
    *(uint4*)(g_inf + d) = hv;
}

__global__ void __launch_bounds__(256)
split_w_kernel(const float* __restrict__ ipw, const float* __restrict__ outw)
{
    size_t i = (size_t)blockIdx.x * 256 + threadIdx.x;
    int r = (int)(i >> 6);
    int kk = ((int)i & 63) * 8;
    int kt = kk >> 5, km = kk & 31;
    const float* src = (r < 1536) ? (ipw + ((size_t)r << 9) + kk)
                                  : (outw + ((size_t)(r - 1536) << 9) + kk);
    float4 a = *(const float4*)src;
    float4 b = *(const float4*)(src + 4);
    float v[8] = {a.x, a.y, a.z, a.w, b.x, b.y, b.z, b.w};
    uint32_t hw[4], lw[4];
#pragma unroll
    for (int j = 0; j < 4; j++) {
        __half h0 = __float2half_rn(v[2*j]);
        __half h1 = __float2half_rn(v[2*j+1]);
        __half l0 = __float2half_rn(v[2*j]   - __half2float(h0));
        __half l1 = __float2half_rn(v[2*j+1] - __half2float(h1));
        __half2 hp(h0, h1), lp(l0, l1);
        hw[j] = *(uint32_t*)&hp; lw[j] = *(uint32_t*)&lp;
    }
    size_t d = ((size_t)kt * WR + r) * RSTR + km;
    *(uint4*)(g_wh + d) = make_uint4(hw[0], hw[1], hw[2], hw[3]);
    *(uint4*)(g_wl + d) = make_uint4(lw[0], lw[1], lw[2], lw[3]);
}

// ============================================================================
// fp16 asymmetric-split GEMM, bulk 2-stage.
// C = A[MxK] @ (Wh+Wl)[NxK]^T + bias
// ============================================================================
#define TBM 128
#define TBN 128
#define MATW (TBM * RSTR / 2)
#define GSTW (3 * MATW)
#define GEMM_SMEM (2 * GSTW * 4 + 16)

__device__ __forceinline__ void gemm_core(
    const __half* __restrict__ A, int AR, int arow0,
    const __half* __restrict__ Wh, const __half* __restrict__ Wl,
    int brow0,
    const float* __restrict__ bias, void* __restrict__ Cout, int mode,
    uint32_t* smem)
{
    const int tid  = threadIdx.x;
    const int w    = tid >> 5;
    const int lane = tid & 31;
    const int g = lane >> 2, t = lane & 3;
    const int wm = w >> 2, wn = w & 3;
    const int m0 = wm * 64, n0 = wn * 32;
    const int bm = blockIdx.y * TBM;
    const int bn = blockIdx.x * TBN;
    const uint32_t sbase = (uint32_t)__cvta_generic_to_shared(smem);
    const uint32_t mb0 = sbase + 2u * GSTW * 4u;
    const uint32_t mb1 = mb0 + 8u;
    const uint32_t STB = GSTW * 4u;

    float acc[4][4][4];
#pragma unroll
    for (int mt = 0; mt < 4; mt++)
#pragma unroll
        for (int nt = 0; nt < 4; nt++)
#pragma unroll
            for (int u = 0; u < 4; u++) acc[mt][nt][u] = 0.f;

    if (tid == 0) { mbar_init(mb0, 1); mbar_init(mb1, 1); }
    fence_async_init();
    __syncthreads();

    auto issue = [&](int ss, int kt) {
        const uint32_t base = sbase + (uint32_t)ss * GSTW * 4u;
        const uint32_t mb = ss ? mb1 : mb0;
        if (tid < 3) {
            const __half* src;
            size_t off;
            if (tid == 0) {
                src = A;
                off = ((size_t)kt * AR + arow0 + bm) * RSTR;   // FIX: AR, not AIR
            } else {
                src = (tid == 1) ? Wh : Wl;
                off = ((size_t)kt * WR + brow0 + bn) * RSTR;
            }
            bulk_g2s(base + (uint32_t)tid * MATW * 4u, src + off, MATW * 4u, mb);
        }
    };

    if (tid == 0) mbar_expect(mb0, STB);
    __syncthreads();
    issue(0, 0);

    for (int kt = 0; kt < NKT; kt++) {
        const int s = kt & 1;
        if (kt < NKT - 1) {
            if (tid == 0) mbar_expect(s ? mb0 : mb1, STB);
            __syncthreads();
            issue(s ^ 1, kt + 1);
        }
        mbar_wait(s ? mb1 : mb0, (uint32_t)((kt >> 1) & 1));

        const uint32_t* Sw  = smem + s * GSTW;
        const uint32_t* AW  = Sw;
        const uint32_t* WhW = Sw + MATW;
        const uint32_t* WlW = Sw + 2 * MATW;

#pragma unroll
        for (int ks = 0; ks < 2; ks++) {
            uint32_t bhf[4][2], blf[4][2];
#pragma unroll
            for (int nt = 0; nt < 4; nt++) {
                int wb = (n0 + nt * 8 + g) * (RSTR / 2) + ks * 8 + t;
                bhf[nt][0] = WhW[wb]; bhf[nt][1] = WhW[wb + 4];
                blf[nt][0] = WlW[wb]; blf[nt][1] = WlW[wb + 4];
            }
#pragma unroll
            for (int mt = 0; mt < 4; mt++) {
                int wa = (m0 + mt * 16 + g) * (RSTR / 2) + ks * 8 + t;
                uint32_t a0 = AW[wa],     a1 = AW[wa + 8 * (RSTR / 2)];
                uint32_t a2 = AW[wa + 4], a3 = AW[wa + 8 * (RSTR / 2) + 4];
#pragma unroll
                for (int nt = 0; nt < 4; nt++) {
                    mma_f16(acc[mt][nt], a0, a1, a2, a3, bhf[nt][0], bhf[nt][1]);
                    mma_f16(acc[mt][nt], a0, a1, a2, a3, blf[nt][0], blf[nt][1]);
                }
            }
        }
    }

    // epilogue
#pragma unroll
    for (int mt = 0; mt < 4; mt++) {
#pragma unroll
        for (int nt = 0; nt < 4; nt++) {
            int r = bm + m0 + mt * 16 + g;
            int c = bn + n0 + nt * 8 + 2 * t;
            float bx = bias[c], by = bias[c + 1];
            float2 v0 = make_float2(acc[mt][nt][0] + bx, acc[mt][nt][1] + by);
            float2 v1 = make_float2(acc[mt][nt][2] + bx, acc[mt][nt][3] + by);
            if (mode == 0) {
                float* C = (float*)Cout;
                *(float2*)(C + (size_t)r * HDIM + c) = v0;
                *(float2*)(C + (size_t)(r + 8) * HDIM + c) = v1;
            } else if (mode == 1) {
                int b_ = r >> 10, sr = r & 1023, h_ = c >> 6, d0 = c & 63;
                __half* base = (__half*)Cout +
                    ((size_t)(b_ * NHEAD + h_) * SEQ + sr) * PADKH + d0;
                *(__half2*)base = __floats2half2_rn(v0.x, v0.y);
                *(__half2*)(base + (size_t)8 * PADKH) = __floats2half2_rn(v1.x, v1.y);
            } else {
                int b_ = r >> 10, sr = r & 1023, h_ = c >> 6;
                int kb = sr >> 5, kin = sr & 31, d0 = c & 63;
                __half* base = (__half*)Cout +
                    (((size_t)(b_ * NHEAD + h_) * (SEQ / KB) + kb) * DHEAD) * PADVTH;
                base[(size_t)d0 * PADVTH + kin]           = __float2half_rn(v0.x);
                base[(size_t)(d0 + 1) * PADVTH + kin]     = __float2half_rn(v0.y);
                base[(size_t)d0 * PADVTH + kin + 8]       = __float2half_rn(v1.x);
                base[(size_t)(d0 + 1) * PADVTH + kin + 8] = __float2half_rn(v1.y);
            }
        }
    }
}

__global__ void __launch_bounds__(256, 2)
qkv_gemm_kernel(const float* __restrict__ ipb)
{
    extern __shared__ uint32_t smem_g[];
    const int z = blockIdx.z;
    void* outp = (z == 0) ? (void*)g_q : (z == 1) ? (void*)g_kh : (void*)g_vth;
    gemm_core(g_inf, AIR, z * ROWS,
              g_wh, g_wl, z * HDIM,
              ipb + z * HDIM, outp, z, smem_g);
}

__global__ void __launch_bounds__(256, 2)
outproj_kernel(const float* __restrict__ outb, float* __restrict__ out)
{
    extern __shared__ uint32_t smem_g[];
    gemm_core(g_af, ROWS, 0,
              g_wh, g_wl, 3 * HDIM,
              outb, out, 0, smem_g);
}

// ============================================================================
// fp16 flash attention (R14 mainloop); epilogue emits single fp16.
// ============================================================================
#define QB 128
#define PADB 132
#define PADM 40
#define ST_V 4608
#define ST_B (ST_V + 5120)
#define ST_M (ST_B + KB*PADB*4)
#define ST_BYTES (ST_M + QB*PADM*4)
#define ATTN_TX (4608 + 5120 + KB*512 + QB*128)
#define ATTN_SMEM (2 * ST_BYTES + 16)

__global__ void __launch_bounds__(256, 2)
attn_mma_kernel(const float* __restrict__ kern,
                const uint32_t* __restrict__ amask, float scale)
{
    extern __shared__ char smc[];
    const uint32_t sbase = (uint32_t)__cvta_generic_to_shared(smc);
    const uint32_t mb0 = sbase + 2u * ST_BYTES;
    const uint32_t mb1 = mb0 + 8u;

    const int bh = blockIdx.y, b = bh >> 3, h = bh & 7;
    const int qb = blockIdx.x * QB;
    const int tid  = threadIdx.x;
    const int w    = tid >> 5;
    const int lane = tid & 31;
    const int g = lane >> 2, t = lane & 3;

    const int m_  = lane >> 3, r_ = lane & 7;
    const int flo = m_ >> 1, hh = m_ & 1;
    const uint32_t klane = (uint32_t)((flo * 8 + r_) * (PADKH * 2) + hh * 16);
    const uint32_t vlane = (uint32_t)((flo * 8 + r_) * (PADVTH * 2) + hh * 16);

    const float*  Qg = g_q + (size_t)b * SEQ * HDIM + h * DHEAD;
    const __half* Kp = g_kh + (size_t)bh * SEQ * PADKH;
    const __half* Vt = g_vth + (size_t)bh * (SEQ / KB) * DHEAD * PADVTH;
    const float* kern_bh = kern + (size_t)bh * SEQ * SEQ;
    const uint32_t* mask_bh = amask + (size_t)bh * SEQ * SEQ;

    if (tid == 0) { mbar_init(mb0, 1); mbar_init(mb1, 1); }
    fence_async_init();
    __syncthreads();

    auto issue = [&](int ss, int kb) {
        const uint32_t base = sbase + (uint32_t)ss * ST_BYTES;
        const uint32_t mb = ss ? mb1 : mb0;
        if (tid == 0)
            bulk_g2s(base, Kp + (size_t)kb * KB * PADKH, 4608u, mb);
        else if (tid == 1)
            bulk_g2s(base + ST_V, Vt + (size_t)kb * DHEAD * PADVTH, 5120u, mb);
        else if (tid >= 32 && tid < 64) {
            int r = tid - 32;
            bulk_g2s(base + (uint32_t)(ST_B + r * PADB * 4),
                     kern_bh + (size_t)(kb * KB + r) * SEQ + qb, 512u, mb);
        } else if (tid >= 64 && tid < 192) {
            int r = tid - 64;
            bulk_g2s(base + (uint32_t)(ST_M + r * PADM * 4),
                     mask_bh + (size_t)(qb + r) * SEQ + kb * KB, 128u, mb);
        }
    };

    if (tid == 0) mbar_expect(mb0, ATTN_TX);
    __syncthreads();
    issue(0, 0);

    // Q fragments, pre-scaled (exact: 2^-3)
    uint32_t qa[4][4];
    {
        const float* Qr0 = Qg + (size_t)(qb + w * 16 + g) * HDIM;
        const float* Qr1 = Qr0 + 8 * (size_t)HDIM;
#pragma unroll
        for (int kk = 0; kk < 4; kk++) {
            int d0 = 16 * kk + 2 * t;
            float2 x0 = *(const float2*)(Qr0 + d0);
            float2 x1 = *(const float2*)(Qr1 + d0);
            float2 x2 = *(const float2*)(Qr0 + d0 + 8);
            float2 x3 = *(const float2*)(Qr1 + d0 + 8);
            qa[kk][0] = packh2(x0.x * scale, x0.y * scale);
            qa[kk][1] = packh2(x1.x * scale, x1.y * scale);
            qa[kk][2] = packh2(x2.x * scale, x2.y * scale);
            qa[kk][3] = packh2(x3.x * scale, x3.y * scale);
        }
    }

    float o[8][4];
#pragma unroll
    for (int f = 0; f < 8; f++)
#pragma unroll
        for (int u = 0; u < 4; u++) o[f][u] = 0.f;
    float m_run[2] = {-1e30f, -1e30f}, l_run[2] = {0.f, 0.f};

    const int qrl0 = w * 16 + g;

    const int NT = SEQ / KB;
    for (int kb = 0; kb < NT; kb++) {
        const int s = kb & 1;
        if (kb < NT - 1) {
            if (tid == 0) mbar_expect(s ? mb0 : mb1, ATTN_TX);
            __syncthreads();
            issue(s ^ 1, kb + 1);
        }
        mbar_wait(s ? mb1 : mb0, (uint32_t)((kb >> 1) & 1));

        const char* Sb = smc + (size_t)s * ST_BYTES;
        const uint32_t stg = sbase + (uint32_t)s * ST_BYTES;
        const float*  Bs = (const float*)(Sb + ST_B);
        const uint32_t* Ms = (const uint32_t*)(Sb + ST_M);

        // ---- S accumulators initialized with the bias tile ----
        float sc[4][4];
#pragma unroll
        for (int f = 0; f < 4; f++) {
            int kc = f * 8 + 2 * t;
            sc[f][0] = Bs[kc * PADB + qrl0];
            sc[f][1] = Bs[(kc + 1) * PADB + qrl0];
            sc[f][2] = Bs[kc * PADB + qrl0 + 8];
            sc[f][3] = Bs[(kc + 1) * PADB + qrl0 + 8];
        }

        // ---- S += (scale*Q) K^T : LDSM.x4 fragments ----
#pragma unroll
        for (int kk = 0; kk < 4; kk++) {
#pragma unroll
            for (int j = 0; j < 2; j++) {
                uint32_t b00, b01, b10, b11;
                ldsm4(b00, b01, b10, b11,
                      stg + klane + (uint32_t)(j * 16 * PADKH * 2 + kk * 32));
                mma_f16(sc[2 * j],     qa[kk][0], qa[kk][1], qa[kk][2], qa[kk][3], b00, b01);
                mma_f16(sc[2 * j + 1], qa[kk][0], qa[kk][1], qa[kk][2], qa[kk][3], b10, b11);
            }
        }

        // ---- mask + online softmax (no exp guard) ----
#pragma unroll
        for (int e = 0; e < 2; e++) {
            const int qrl = qrl0 + e * 8;
            const uint2* Mrow = (const uint2*)(Ms + qrl * PADM);
            float rmax = -1e30f;
#pragma unroll
            for (int f = 0; f < 4; f++) {
                uint2 mw = Mrow[f * 4 + t];
                float s0 = sc[f][e * 2 + 0];
                float s1 = sc[f][e * 2 + 1];
                s0 = mw.x ? -1e30f : s0;
                s1 = mw.y ? -1e30f : s1;
                sc[f][e * 2 + 0] = s0;
                sc[f][e * 2 + 1] = s1;
                rmax = fmaxf(rmax, fmaxf(s0, s1));
            }
            rmax = fmaxf(rmax, __shfl_xor_sync(0xffffffffu, rmax, 1));
            rmax = fmaxf(rmax, __shfl_xor_sync(0xffffffffu, rmax, 2));
            float mn = fmaxf(m_run[e], rmax);
            float fe = __expf(m_run[e] - mn);
            float ps = 0.f;
#pragma unroll
            for (int f = 0; f < 4; f++) {
#pragma unroll
                for (int u = 0; u < 2; u++) {
                    float p = __expf(sc[f][e * 2 + u] - mn);
                    sc[f][e * 2 + u] = p;
                    ps += p;
                }
            }
            ps += __shfl_xor_sync(0xffffffffu, ps, 1);
            ps += __shfl_xor_sync(0xffffffffu, ps, 2);
            l_run[e] = l_run[e] * fe + ps;
            m_run[e] = mn;
#pragma unroll
            for (int f = 0; f < 4; f++) {
                o[2 * f][e * 2 + 0] *= fe;     o[2 * f][e * 2 + 1] *= fe;
                o[2 * f + 1][e * 2 + 0] *= fe; o[2 * f + 1][e * 2 + 1] *= fe;
            }
        }

        // ---- O += P @ V ----
#pragma unroll
        for (int kk = 0; kk < 2; kk++) {
            uint32_t a0 = packh2(sc[2 * kk][0],     sc[2 * kk][1]);
            uint32_t a1 = packh2(sc[2 * kk][2],     sc[2 * kk][3]);
            uint32_t a2 = packh2(sc[2 * kk + 1][0], sc[2 * kk + 1][1]);
            uint32_t a3 = packh2(sc[2 * kk + 1][2], sc[2 * kk + 1][3]);
#pragma unroll
            for (int j = 0; j < 4; j++) {
                uint32_t v00, v01, v10, v11;
                ldsm4(v00, v01, v10, v11,
                      stg + (uint32_t)ST_V + vlane +
                      (uint32_t)(j * 16 * PADVTH * 2 + kk * 32));
                mma_f16(o[2 * j],     a0, a1, a2, a3, v00, v01);
                mma_f16(o[2 * j + 1], a0, a1, a2, a3, v10, v11);
            }
        }
    }

    // ---- normalize + write single fp16 in outproj's tiled layout ----
#pragma unroll
    for (int e = 0; e < 2; e++) {
        float inv = 1.0f / l_run[e];
        int qrl = qrl0 + e * 8;
        size_t grow = (size_t)b * SEQ + qb + qrl;
#pragma unroll
        for (int f = 0; f < 8; f++) {
            float x = o[f][e * 2 + 0] * inv;
            float y = o[f][e * 2 + 1] * inv;
            uint32_t hv = packh2(x, y);
            int c = h * DHEAD + f * 8 + 2 * t;
            int kt = c >> 5, km = c & 31;
            size_t off = ((size_t)kt * ROWS + grow) * RSTR + km;
            *(uint32_t*)(g_af + off) = hv;
        }
    }
}

// ============================================================================
// Launch
// ============================================================================
extern "C" void kernel_launch(void* const* d_in, const int* in_sizes, int n_in,
                              void* d_out, int out_size)
{
    const float* query    = (const float*)d_in[0];
    const float* key_     = (const float*)d_in[1];
    const float* value    = (const float*)d_in[2];
    const uint32_t* amask = (const uint32_t*)d_in[3];
    const float* kern     = (const float*)d_in[5];
    const float* ipw      = (const float*)d_in[6];
    const float* ipb      = (const float*)d_in[7];
    const float* outw     = (const float*)d_in[8];
    const float* outb     = (const float*)d_in[9];
    float* out = (float*)d_out;

    cudaFuncSetAttribute(attn_mma_kernel,
                         cudaFuncAttributeMaxDynamicSharedMemorySize, ATTN_SMEM);
    cudaFuncSetAttribute(qkv_gemm_kernel,
                         cudaFuncAttributeMaxDynamicSharedMemorySize, GEMM_SMEM);
    cudaFuncSetAttribute(outproj_kernel,
                         cudaFuncAttributeMaxDynamicSharedMemorySize, GEMM_SMEM);

    convert_in_kernel<<<3 * ROWS * 64 / 256, 256>>>(query, key_, value);
    split_w_kernel<<<WR * 64 / 256, 256>>>(ipw, outw);

    dim3 gq(HDIM / TBN, ROWS / TBM, 3);
    qkv_gemm_kernel<<<gq, 256, GEMM_SMEM>>>(ipb);

    dim3 ga(SEQ / QB, BATCH * NHEAD, 1);
    attn_mma_kernel<<<ga, 256, ATTN_SMEM>>>(kern, amask, 0.125f);

    dim3 go(HDIM / TBN, ROWS / TBM, 1);
    outproj_kernel<<<go, 256, GEMM_SMEM>>>(outb, out);
}